// round 10
// baseline (speedup 1.0000x reference)
#include <cuda_runtime.h>
#include <cuda_fp16.h>
#include <cstdint>

// VectorQuantizer: single-product FP16 mma.sync screen (e pre-scaled x1024 into
// fp16-normal range) + provable-margin exact rescore (warp-parallel).
// 2 CTAs/SM. B=32, D=64, T=8192, K=512.

#define BB 32
#define DD 64
#define TT 8192
#define KK 512
#define TILE_M 128
#define NTILES 2048
#define TILES_PER_B 64
#define NTHREADS 256
#define GRIDX 304
#define ARRSZ ((long long)BB * DD * TT)
#define MARGIN 2e-4f
#define FINF 3.402823466e38f

#define RSTRIDE 144          // 72 fp16 per row (conflict-free ldmatrix)
#define ESCALE 1024.0f
#define EINV  (-0.001953125f)   // -2/1024, exact

// smem byte offsets (per CTA, total 96000 -> 2 CTAs/SM)
#define OFF_QN   0
#define OFF_E2   128       // 512 f -> 2176
#define OFF_X2   2176      // 128 f -> 2688
#define OFF_WIN  2688      // 128 i -> 3200
#define OFF_QUE  3200      // 128 i -> 3712
#define OFF_XH   3840      // 128*144 = 18432 -> 22272
#define OFF_EH   22272     // 512*144 = 73728 -> 96000
#define SMEM_TOTAL 96000

__device__ __forceinline__ uint32_t smem_u32(const void* p) {
    uint32_t a;
    asm("{ .reg .u64 t; cvta.to.shared.u64 t, %1; cvt.u32.u64 %0, t; }" : "=r"(a) : "l"(p));
    return a;
}
__device__ __forceinline__ void ldsm_x4(uint32_t& r0, uint32_t& r1, uint32_t& r2, uint32_t& r3,
                                        uint32_t addr) {
    asm volatile("ldmatrix.sync.aligned.m8n8.x4.shared.b16 {%0,%1,%2,%3}, [%4];"
                 : "=r"(r0), "=r"(r1), "=r"(r2), "=r"(r3) : "r"(addr));
}
__device__ __forceinline__ void mma_f16(float* c, const uint32_t* a, uint32_t b0, uint32_t b1) {
    asm volatile("mma.sync.aligned.m16n8k16.row.col.f32.f16.f16.f32 "
                 "{%0,%1,%2,%3}, {%4,%5,%6,%7}, {%8,%9}, {%0,%1,%2,%3};"
                 : "+f"(c[0]), "+f"(c[1]), "+f"(c[2]), "+f"(c[3])
                 : "r"(a[0]), "r"(a[1]), "r"(a[2]), "r"(a[3]), "r"(b0), "r"(b1));
}
__device__ __forceinline__ uint32_t pack_h2(float lo, float hi) {
    __half2 h = __floats2half2_rn(lo, hi);
    return *reinterpret_cast<uint32_t*>(&h);
}
__device__ __forceinline__ void top2(float dd, int k, float& d1, float& d2, int& i1) {
    if (dd < d1) { d2 = d1; d1 = dd; i1 = k; }
    else if (dd < d2) { d2 = dd; }
}

extern __shared__ __align__(1024) char smem[];

__global__ void __launch_bounds__(NTHREADS, 2)
vq_f16_kernel(const float* __restrict__ x,
              const float* __restrict__ emb,
              float* __restrict__ out) {
    const int tid  = threadIdx.x;
    const int wid  = tid >> 5;
    const int lane = tid & 31;
    const uint32_t sb = smem_u32(smem);

    float* s_e2  = (float*)(smem + OFF_E2);
    float* s_x2  = (float*)(smem + OFF_X2);
    int*   s_win = (int*)(smem + OFF_WIN);
    int*   s_que = (int*)(smem + OFF_QUE);
    int*   s_qn  = (int*)(smem + OFF_QN);

    // ---- Prologue: codebook -> exact e2 chain + fp16 rows (e * 1024) ----
    for (int r = tid; r < KK; r += NTHREADS) {
        float ev[DD];
        const float4* er = (const float4*)(emb + r * DD);
        #pragma unroll
        for (int g = 0; g < DD / 4; g++) {
            float4 v = er[g];
            ev[g*4+0] = v.x; ev[g*4+1] = v.y; ev[g*4+2] = v.z; ev[g*4+3] = v.w;
        }
        float s = 0.0f;
        #pragma unroll
        for (int d = 0; d < DD; d++) s = __fadd_rn(s, __fmul_rn(ev[d], ev[d]));
        s_e2[r] = s;
        #pragma unroll
        for (int d = 0; d < DD; d += 2)
            *(uint32_t*)(smem + OFF_EH + r * RSTRIDE + d * 2) =
                pack_h2(ev[d] * ESCALE, ev[d+1] * ESCALE);
    }

    float* o_st = out;
    float* o_q  = out + ARRSZ;

    const int lane4 = lane & 3;
    const int laneg = lane >> 2;
    const uint32_t a_off = (uint32_t)((lane & 15) * RSTRIDE + (lane >> 4) * 16);
    const uint32_t b_off = (uint32_t)((((lane & 7) + ((lane >> 4) << 3)) * RSTRIDE) +
                                      (((lane >> 3) & 1) * 16));

    for (int tile = blockIdx.x; tile < NTILES; tile += GRIDX) {
        const int b  = tile / TILES_PER_B;
        const int t0 = (tile % TILES_PER_B) * TILE_M;
        const float* xb = x + (long long)b * DD * TT + t0;
        const long long obase = (long long)b * DD * TT;

        // ---- Phase A: load x (threads 0..127), exact x2 chain, fp16 rows ----
        if (tid == 0) *s_qn = 0;
        if (tid < TILE_M) {
            const int tt = tid;
            float xv[DD];
            #pragma unroll
            for (int d = 0; d < DD; d++) xv[d] = xb[(long long)d * TT + tt];
            float s = 0.0f;
            #pragma unroll
            for (int d = 0; d < DD; d++) s = __fadd_rn(s, __fmul_rn(xv[d], xv[d]));
            s_x2[tt] = s;
            #pragma unroll
            for (int d = 0; d < DD; d += 2)
                *(uint32_t*)(smem + OFF_XH + tt * RSTRIDE + d * 2) =
                    pack_h2(xv[d], xv[d+1]);
        }
        __syncthreads();

        // ---- Phase B: screen. warp w: tokens [16w,16w+16), all 512 codes ----
        {
            const int m0 = wid * 16;
            uint32_t ah[4][4];
            const uint32_t abh = sb + OFF_XH + m0 * RSTRIDE + a_off;
            #pragma unroll
            for (int s = 0; s < 4; s++)
                ldsm_x4(ah[s][0], ah[s][1], ah[s][2], ah[s][3], abh + s * 32);

            float d1a = FINF, d2a = FINF, d1b = FINF, d2b = FINF;
            int   i1a = 0, i1b = 0;
            const uint32_t bbh = sb + OFF_EH + b_off;

            #pragma unroll 1
            for (int c = 0; c < 8; c++) {
                const int n0 = c * 64;
                #pragma unroll 2
                for (int p = 0; p < 4; p++) {
                    float acc0[4] = {0.f, 0.f, 0.f, 0.f};
                    float acc1[4] = {0.f, 0.f, 0.f, 0.f};
                    const uint32_t bt = bbh + (uint32_t)((n0 + 16 * p) * RSTRIDE);
                    #pragma unroll
                    for (int s = 0; s < 4; s++) {
                        uint32_t b0, b1, b2, b3;
                        ldsm_x4(b0, b1, b2, b3, bt + s * 32);
                        mma_f16(acc0, ah[s], b0, b1);
                        mma_f16(acc1, ah[s], b2, b3);
                    }
                    // acc = 1024*xe ; screen dist (x2 dropped): e2 - 2*xe
                    const int cb0 = n0 + 16 * p + 2 * lane4;
                    const int cb1 = cb0 + 8;
                    const float e00 = s_e2[cb0], e01 = s_e2[cb0 + 1];
                    const float e10 = s_e2[cb1], e11 = s_e2[cb1 + 1];
                    float dd;
                    dd = fmaf(EINV, acc0[0], e00); top2(dd, cb0,     d1a, d2a, i1a);
                    dd = fmaf(EINV, acc0[1], e01); top2(dd, cb0 + 1, d1a, d2a, i1a);
                    dd = fmaf(EINV, acc0[2], e00); top2(dd, cb0,     d1b, d2b, i1b);
                    dd = fmaf(EINV, acc0[3], e01); top2(dd, cb0 + 1, d1b, d2b, i1b);
                    dd = fmaf(EINV, acc1[0], e10); top2(dd, cb1,     d1a, d2a, i1a);
                    dd = fmaf(EINV, acc1[1], e11); top2(dd, cb1 + 1, d1a, d2a, i1a);
                    dd = fmaf(EINV, acc1[2], e10); top2(dd, cb1,     d1b, d2b, i1b);
                    dd = fmaf(EINV, acc1[3], e11); top2(dd, cb1 + 1, d1b, d2b, i1b);
                }
            }

            // quad reduce (lanes xor 1, 2) lexicographic (d, k)
            #pragma unroll
            for (int m = 1; m <= 2; m <<= 1) {
                float od = __shfl_xor_sync(0xffffffffu, d1a, m);
                int   oi = __shfl_xor_sync(0xffffffffu, i1a, m);
                float o2 = __shfl_xor_sync(0xffffffffu, d2a, m);
                bool take = (od < d1a) || (od == d1a && oi < i1a);
                float nd2 = take ? fminf(d1a, o2) : fminf(d2a, od);
                if (take) { d1a = od; i1a = oi; }
                d2a = nd2;
                od = __shfl_xor_sync(0xffffffffu, d1b, m);
                oi = __shfl_xor_sync(0xffffffffu, i1b, m);
                o2 = __shfl_xor_sync(0xffffffffu, d2b, m);
                take = (od < d1b) || (od == d1b && oi < i1b);
                nd2 = take ? fminf(d1b, o2) : fminf(d2b, od);
                if (take) { d1b = od; i1b = oi; }
                d2b = nd2;
            }
            if (lane4 == 0) {
                const int r0 = m0 + laneg, r1 = r0 + 8;
                s_win[r0] = i1a;
                if (!(d2a - d1a > MARGIN)) { int q = atomicAdd(s_qn, 1); s_que[q] = r0; }
                s_win[r1] = i1b;
                if (!(d2b - d1b > MARGIN)) { int q = atomicAdd(s_qn, 1); s_que[q] = r1; }
            }
        }
        __syncthreads();

        // ---- Phase E: warp-parallel exact rescore (reference chain) ----
        {
            const int nq = *s_qn;
            for (int j = wid; j < nq; j += 8) {
                const int tt = s_que[j];
                const float x2t = s_x2[tt];
                // lane owns codes [lane*16, lane*16+16), ascending
                float ps[16];
                #pragma unroll
                for (int kk = 0; kk < 16; kk++) ps[kk] = 0.0f;
                #pragma unroll 1
                for (int half = 0; half < 2; half++) {
                    float xr[32];
                    #pragma unroll
                    for (int d = 0; d < 32; d++)
                        xr[d] = __ldg(xb + (long long)(half * 32 + d) * TT + tt);
                    #pragma unroll 1
                    for (int kk = 0; kk < 16; kk++) {
                        const float4* e0 =
                            (const float4*)(emb + (lane * 16 + kk) * DD + half * 32);
                        float s0 = ps[kk];
                        #pragma unroll
                        for (int g = 0; g < 8; g++) {
                            float4 v = __ldg(e0 + g);
                            s0 = fmaf(xr[g*4+0], v.x, s0);
                            s0 = fmaf(xr[g*4+1], v.y, s0);
                            s0 = fmaf(xr[g*4+2], v.z, s0);
                            s0 = fmaf(xr[g*4+3], v.w, s0);
                        }
                        ps[kk] = s0;
                    }
                }
                float bd = FINF; int bk = 0;
                #pragma unroll
                for (int kk = 0; kk < 16; kk++) {
                    const int k = lane * 16 + kk;
                    float dA = __fadd_rn(__fsub_rn(x2t, 2.0f * ps[kk]), s_e2[k]);
                    if (dA < bd) { bd = dA; bk = k; }
                }
                #pragma unroll
                for (int off = 16; off; off >>= 1) {
                    float od = __shfl_down_sync(0xFFFFFFFFu, bd, off);
                    int   ok = __shfl_down_sync(0xFFFFFFFFu, bk, off);
                    if (od < bd || (od == bd && ok < bk)) { bd = od; bk = ok; }
                }
                if (lane == 0) s_win[tt] = bk;
            }
        }
        __syncthreads();

        // ---- Phase F: direct output writes (token pairs, float2) ----
        {
            const int pr = tid & 63;          // token pair: (2pr, 2pr+1)
            const int qd = tid >> 6;          // d quarter: [16qd, 16qd+16)
            const int ta = 2 * pr;
            const int ka = s_win[ta], kb = s_win[ta + 1];
            const float4* ea = (const float4*)(emb + ka * DD + qd * 16);
            const float4* eb = (const float4*)(emb + kb * DD + qd * 16);
            float qa[16], qb[16];
            #pragma unroll
            for (int g = 0; g < 4; g++) {
                float4 va = __ldg(ea + g);
                qa[g*4+0] = va.x; qa[g*4+1] = va.y; qa[g*4+2] = va.z; qa[g*4+3] = va.w;
                float4 vb = __ldg(eb + g);
                qb[g*4+0] = vb.x; qb[g*4+1] = vb.y; qb[g*4+2] = vb.z; qb[g*4+3] = vb.w;
            }
            #pragma unroll
            for (int i = 0; i < 16; i++) {
                const int d = qd * 16 + i;
                const float2 xv = *(const float2*)(xb + (long long)d * TT + ta);
                float2 stv = make_float2(__fadd_rn(xv.x, __fsub_rn(qa[i], xv.x)),
                                         __fadd_rn(xv.y, __fsub_rn(qb[i], xv.y)));
                float2 qv = make_float2(qa[i], qb[i]);
                const long long o = obase + (long long)d * TT + t0 + ta;
                *(float2*)(o_st + o) = stv;
                *(float2*)(o_q + o)  = qv;
            }
        }
        __syncthreads();
    }
}

extern "C" void kernel_launch(void* const* d_in, const int* in_sizes, int n_in,
                              void* d_out, int out_size) {
    const float* x   = (const float*)d_in[0];
    const float* emb = (const float*)d_in[1];
    float* out = (float*)d_out;
    (void)in_sizes; (void)n_in; (void)out_size;

    cudaFuncSetAttribute(vq_f16_kernel,
                         cudaFuncAttributeMaxDynamicSharedMemorySize, SMEM_TOTAL);
    vq_f16_kernel<<<GRIDX, NTHREADS, SMEM_TOTAL>>>(x, emb, out);
}